// round 1
// baseline (speedup 1.0000x reference)
#include <cuda_runtime.h>
#include <math.h>

// Problem constants
#define BB 8
#define TT 2048
#define DD 1024
#define MTOT (BB * TT)        // 16384 rows
#define QKV_LD 3072           // q|k|v packed per row

// 1/sqrt(D*T) = 1/sqrt(2097152)
#define INV_SCALE 6.9053396600248781e-04f

// Scratch (device globals: cudaMalloc is banned)
__device__ float g_qkv[(size_t)MTOT * QKV_LD];      // [row, 0:1024)=q [1024:2048)=k [2048:3072)=v
__device__ float g_scores[(size_t)BB * TT * TT];    // [b, i, j] lower triangle valid
__device__ float g_y[(size_t)MTOT * DD];

// ---------------------------------------------------------------------------
// Kernel 1: qkv = x @ W_qkv^T + b_qkv
// A = x [16384, 1024] row-major; B = W [3072, 1024] row-major; C = g_qkv [16384, 3072]
// Tile 128x128x16, 256 threads, 8x8 per-thread micro-tile.
// ---------------------------------------------------------------------------
__global__ __launch_bounds__(256) void k_qkv(const float* __restrict__ X,
                                             const float* __restrict__ W,
                                             const float* __restrict__ bias) {
    __shared__ float As[16][128];
    __shared__ float Bs[16][128];

    const int m0 = blockIdx.y * 128;
    const int n0 = blockIdx.x * 128;
    const int tid = threadIdx.x;
    const int tx = tid & 15;        // 0..15 -> n
    const int ty = tid >> 4;        // 0..15 -> m

    const int lr = tid >> 2;        // 0..63 loader row
    const int lc = (tid & 3) * 4;   // 0,4,8,12 loader col (k)

    float acc[8][8];
#pragma unroll
    for (int i = 0; i < 8; i++)
#pragma unroll
        for (int j = 0; j < 8; j++) acc[i][j] = 0.0f;

    for (int k0 = 0; k0 < 1024; k0 += 16) {
#pragma unroll
        for (int h = 0; h < 2; h++) {
            const int row = lr + h * 64;
            float4 va = *(const float4*)(X + (size_t)(m0 + row) * 1024 + k0 + lc);
            As[lc + 0][row] = va.x; As[lc + 1][row] = va.y;
            As[lc + 2][row] = va.z; As[lc + 3][row] = va.w;
            float4 vb = *(const float4*)(W + (size_t)(n0 + row) * 1024 + k0 + lc);
            Bs[lc + 0][row] = vb.x; Bs[lc + 1][row] = vb.y;
            Bs[lc + 2][row] = vb.z; Bs[lc + 3][row] = vb.w;
        }
        __syncthreads();
#pragma unroll
        for (int kk = 0; kk < 16; kk++) {
            float4 a0 = *(const float4*)&As[kk][ty * 8];
            float4 a1 = *(const float4*)&As[kk][ty * 8 + 4];
            float4 b0 = *(const float4*)&Bs[kk][tx * 8];
            float4 b1 = *(const float4*)&Bs[kk][tx * 8 + 4];
            float a[8] = {a0.x, a0.y, a0.z, a0.w, a1.x, a1.y, a1.z, a1.w};
            float b[8] = {b0.x, b0.y, b0.z, b0.w, b1.x, b1.y, b1.z, b1.w};
#pragma unroll
            for (int i = 0; i < 8; i++)
#pragma unroll
                for (int j = 0; j < 8; j++) acc[i][j] += a[i] * b[j];
        }
        __syncthreads();
    }

#pragma unroll
    for (int i = 0; i < 8; i++) {
        const int m = m0 + ty * 8 + i;
#pragma unroll
        for (int j = 0; j < 8; j++) {
            const int n = n0 + tx * 8 + j;
            g_qkv[(size_t)m * QKV_LD + n] = acc[i][j] + bias[n];
        }
    }
}

// ---------------------------------------------------------------------------
// Kernel 2: scores[b,i,j] = (q_i . k_j) * INV_SCALE  for j <= i (causal)
// Lower-triangle tiles only; diagonal tile masked elementwise.
// ---------------------------------------------------------------------------
__global__ __launch_bounds__(256) void k_scores() {
    const int b  = blockIdx.z;
    const int it = blockIdx.y;
    const int jt = blockIdx.x;
    if (jt > it) return;

    __shared__ float As[16][128];
    __shared__ float Bs[16][128];

    const float* Q = g_qkv + (size_t)b * TT * QKV_LD;          // q at offset 0
    const float* K = g_qkv + (size_t)b * TT * QKV_LD + 1024;   // k at offset 1024
    float* C = g_scores + (size_t)b * TT * TT;

    const int i0 = it * 128;
    const int j0 = jt * 128;
    const int tid = threadIdx.x;
    const int tx = tid & 15;
    const int ty = tid >> 4;
    const int lr = tid >> 2;
    const int lc = (tid & 3) * 4;

    float acc[8][8];
#pragma unroll
    for (int i = 0; i < 8; i++)
#pragma unroll
        for (int j = 0; j < 8; j++) acc[i][j] = 0.0f;

    for (int k0 = 0; k0 < 1024; k0 += 16) {
#pragma unroll
        for (int h = 0; h < 2; h++) {
            const int row = lr + h * 64;
            float4 va = *(const float4*)(Q + (size_t)(i0 + row) * QKV_LD + k0 + lc);
            As[lc + 0][row] = va.x; As[lc + 1][row] = va.y;
            As[lc + 2][row] = va.z; As[lc + 3][row] = va.w;
            float4 vb = *(const float4*)(K + (size_t)(j0 + row) * QKV_LD + k0 + lc);
            Bs[lc + 0][row] = vb.x; Bs[lc + 1][row] = vb.y;
            Bs[lc + 2][row] = vb.z; Bs[lc + 3][row] = vb.w;
        }
        __syncthreads();
#pragma unroll
        for (int kk = 0; kk < 16; kk++) {
            float4 a0 = *(const float4*)&As[kk][ty * 8];
            float4 a1 = *(const float4*)&As[kk][ty * 8 + 4];
            float4 b0 = *(const float4*)&Bs[kk][tx * 8];
            float4 b1 = *(const float4*)&Bs[kk][tx * 8 + 4];
            float a[8] = {a0.x, a0.y, a0.z, a0.w, a1.x, a1.y, a1.z, a1.w};
            float b[8] = {b0.x, b0.y, b0.z, b0.w, b1.x, b1.y, b1.z, b1.w};
#pragma unroll
            for (int i = 0; i < 8; i++)
#pragma unroll
                for (int j = 0; j < 8; j++) acc[i][j] += a[i] * b[j];
        }
        __syncthreads();
    }

    const bool diag = (it == jt);
#pragma unroll
    for (int i = 0; i < 8; i++) {
        const int gi = i0 + ty * 8 + i;
#pragma unroll
        for (int j = 0; j < 8; j++) {
            const int gj = j0 + tx * 8 + j;
            float v = acc[i][j] * INV_SCALE;
            if (diag && gj > gi) v = 0.0f;
            C[(size_t)gi * TT + gj] = v;
        }
    }
}

// ---------------------------------------------------------------------------
// Kernel 3: y[b,i,d] = sum_{j<=i} scores[b,i,j] * v[b,j,d]
// k-loop runs only to the end of the diagonal tile (upper tiles never read).
// ---------------------------------------------------------------------------
__global__ __launch_bounds__(256) void k_attnv() {
    const int b  = blockIdx.z;
    const int it = blockIdx.y;
    const int dt = blockIdx.x;

    __shared__ float As[16][128];
    __shared__ float Bs[16][128];

    const float* S = g_scores + (size_t)b * TT * TT;           // [2048, 2048]
    const float* V = g_qkv + (size_t)b * TT * QKV_LD + 2048;   // v at offset 2048

    const int i0 = it * 128;
    const int d0 = dt * 128;
    const int kmax = (it + 1) * 128;

    const int tid = threadIdx.x;
    const int tx = tid & 15;
    const int ty = tid >> 4;
    const int lr = tid >> 2;        // A loader
    const int lc = (tid & 3) * 4;
    const int br = tid >> 5;        // B loader: 8 rows/pass
    const int bc = (tid & 31) * 4;

    float acc[8][8];
#pragma unroll
    for (int i = 0; i < 8; i++)
#pragma unroll
        for (int j = 0; j < 8; j++) acc[i][j] = 0.0f;

    for (int k0 = 0; k0 < kmax; k0 += 16) {
        // A tile: scores rows i0.., cols k0..k0+15 (transposed into As)
#pragma unroll
        for (int h = 0; h < 2; h++) {
            const int row = lr + h * 64;
            float4 va = *(const float4*)(S + (size_t)(i0 + row) * TT + k0 + lc);
            As[lc + 0][row] = va.x; As[lc + 1][row] = va.y;
            As[lc + 2][row] = va.z; As[lc + 3][row] = va.w;
        }
        // B tile: v rows k0..k0+15, cols d0..d0+127 (direct layout)
#pragma unroll
        for (int h = 0; h < 2; h++) {
            const int row = br + h * 8;
            float4 vb = *(const float4*)(V + (size_t)(k0 + row) * QKV_LD + d0 + bc);
            *(float4*)&Bs[row][bc] = vb;
        }
        __syncthreads();
#pragma unroll
        for (int kk = 0; kk < 16; kk++) {
            float4 a0 = *(const float4*)&As[kk][ty * 8];
            float4 a1 = *(const float4*)&As[kk][ty * 8 + 4];
            float4 b0 = *(const float4*)&Bs[kk][tx * 8];
            float4 b1 = *(const float4*)&Bs[kk][tx * 8 + 4];
            float a[8] = {a0.x, a0.y, a0.z, a0.w, a1.x, a1.y, a1.z, a1.w};
            float b[8] = {b0.x, b0.y, b0.z, b0.w, b1.x, b1.y, b1.z, b1.w};
#pragma unroll
            for (int i = 0; i < 8; i++)
#pragma unroll
                for (int j = 0; j < 8; j++) acc[i][j] += a[i] * b[j];
        }
        __syncthreads();
    }

#pragma unroll
    for (int i = 0; i < 8; i++) {
        const int m = b * TT + i0 + ty * 8 + i;
#pragma unroll
        for (int j = 0; j < 8; j++) {
            g_y[(size_t)m * DD + d0 + tx * 8 + j] = acc[i][j];
        }
    }
}

// ---------------------------------------------------------------------------
// Kernel 4: LayerNorm over last dim (1024), eps=1e-5, then *ln_w + ln_b
// One block of 256 threads per row; 4 elements (one float4) per thread.
// ---------------------------------------------------------------------------
__global__ __launch_bounds__(256) void k_ln(const float* __restrict__ lnw,
                                            const float* __restrict__ lnb,
                                            float* __restrict__ out) {
    const int row = blockIdx.x;
    const int tid = threadIdx.x;
    const float4 v = ((const float4*)(g_y + (size_t)row * DD))[tid];

    __shared__ float sh[8];
    __shared__ float sh2[8];
    const int wid = tid >> 5, lid = tid & 31;

    float s = v.x + v.y + v.z + v.w;
#pragma unroll
    for (int o = 16; o; o >>= 1) s += __shfl_xor_sync(0xffffffffu, s, o);
    if (lid == 0) sh[wid] = s;
    __syncthreads();
    float mean = 0.0f;
#pragma unroll
    for (int w = 0; w < 8; w++) mean += sh[w];
    mean *= (1.0f / 1024.0f);

    const float dx = v.x - mean, dy = v.y - mean, dz = v.z - mean, dw = v.w - mean;
    float ss = dx * dx + dy * dy + dz * dz + dw * dw;
#pragma unroll
    for (int o = 16; o; o >>= 1) ss += __shfl_xor_sync(0xffffffffu, ss, o);
    if (lid == 0) sh2[wid] = ss;
    __syncthreads();
    float var = 0.0f;
#pragma unroll
    for (int w = 0; w < 8; w++) var += sh2[w];
    var *= (1.0f / 1024.0f);

    const float rstd = rsqrtf(var + 1e-5f);
    const int c = tid * 4;
    float4 o4;
    o4.x = dx * rstd * lnw[c + 0] + lnb[c + 0];
    o4.y = dy * rstd * lnw[c + 1] + lnb[c + 1];
    o4.z = dz * rstd * lnw[c + 2] + lnb[c + 2];
    o4.w = dw * rstd * lnw[c + 3] + lnb[c + 3];
    ((float4*)(out + (size_t)row * DD))[tid] = o4;
}

// ---------------------------------------------------------------------------
extern "C" void kernel_launch(void* const* d_in, const int* in_sizes, int n_in,
                              void* d_out, int out_size) {
    (void)in_sizes; (void)n_in; (void)out_size;
    const float* x    = (const float*)d_in[0];   // [8,2048,1024]
    const float* W    = (const float*)d_in[1];   // [3072,1024]
    const float* bias = (const float*)d_in[2];   // [3072]
    const float* lnw  = (const float*)d_in[3];   // [1024]
    const float* lnb  = (const float*)d_in[4];   // [1024]
    float* out = (float*)d_out;                  // [8,2048,1024]

    k_qkv  <<<dim3(QKV_LD / 128, MTOT / 128), 256>>>(x, W, bias);
    k_scores<<<dim3(TT / 128, TT / 128, BB), 256>>>();
    k_attnv<<<dim3(DD / 128, TT / 128, BB), 256>>>();
    k_ln   <<<MTOT, 256>>>(lnw, lnb, out);
}

// round 5
// speedup vs baseline: 2.3137x; 2.3137x over previous
#include <cuda_runtime.h>
#include <cuda_bf16.h>
#include <stdint.h>

typedef __nv_bfloat16 bf16;

#define BB 8
#define TT 2048
#define DD 1024
#define MTOT (BB * TT)              // 16384
#define QKV_LD 3072
#define INV_SCALE 6.9053396600248781e-04f

// ---- tile geometry ----
#define CHUNK 32                    // k-elements per chunk
#define PITCH 40                    // halves per smem row (80 B) -> conflict-free LDS
#define ROWB (PITCH * 2)            // 80 bytes
#define TILE_BYTES (128 * ROWB)     // 10240
#define BUF_BYTES (4 * TILE_BYTES)  // 40960 (Ah, Al, Bh, Bl)
#define SMEM_DYN (2 * BUF_BYTES)    // 81920

// ---------------- scratch (device globals; cudaMalloc banned) ----------------
__device__ bf16 g_xh[(size_t)MTOT * DD];
__device__ bf16 g_xl[(size_t)MTOT * DD];
__device__ bf16 g_wh[(size_t)3 * DD * DD];
__device__ bf16 g_wl[(size_t)3 * DD * DD];
__device__ bf16 g_qkvh[(size_t)MTOT * QKV_LD];
__device__ bf16 g_qkvl[(size_t)MTOT * QKV_LD];
__device__ bf16 g_vth[(size_t)BB * DD * TT];
__device__ bf16 g_vtl[(size_t)BB * DD * TT];
__device__ bf16 g_sh[(size_t)BB * TT * TT];
__device__ bf16 g_sl[(size_t)BB * TT * TT];
__device__ float g_y[(size_t)MTOT * DD];

// ---------------- PTX helpers (all plain sm_103-baseline features) ----------------
__device__ __forceinline__ uint32_t smem_u32(const void* p) {
    uint32_t a;
    asm("{ .reg .u64 t; cvta.to.shared.u64 t, %1; cvt.u32.u64 %0, t; }" : "=r"(a) : "l"(p));
    return a;
}
__device__ __forceinline__ void cp16(uint32_t dst, const void* src) {
    asm volatile("cp.async.cg.shared.global [%0], [%1], 16;" :: "r"(dst), "l"(src));
}
__device__ __forceinline__ void cp_commit() { asm volatile("cp.async.commit_group;" ::: "memory"); }
template <int N>
__device__ __forceinline__ void cp_wait() { asm volatile("cp.async.wait_group %0;" :: "n"(N) : "memory"); }

__device__ __forceinline__ uint32_t lds_u32(uint32_t a) {
    uint32_t v;
    asm volatile("ld.shared.b32 %0, [%1];" : "=r"(v) : "r"(a));
    return v;
}
__device__ __forceinline__ void mma16816(float* c,
    uint32_t a0, uint32_t a1, uint32_t a2, uint32_t a3, uint32_t b0, uint32_t b1) {
    asm volatile("mma.sync.aligned.m16n8k16.row.col.f32.bf16.bf16.f32 "
        "{%0,%1,%2,%3}, {%4,%5,%6,%7}, {%8,%9}, {%0,%1,%2,%3};"
        : "+f"(c[0]), "+f"(c[1]), "+f"(c[2]), "+f"(c[3])
        : "r"(a0), "r"(a1), "r"(a2), "r"(a3), "r"(b0), "r"(b1));
}

// ---------------- chunk loader: 4 tiles (Ah, Al, Bh, Bl), 128 x 32 halves each ----------------
__device__ __forceinline__ void load_chunk(uint32_t sbuf,
    const bf16* __restrict__ Ah, const bf16* __restrict__ Al, int lda,
    const bf16* __restrict__ Bh, const bf16* __restrict__ Bl, int ldb,
    int k0, int tid)
{
    const bf16* srcs[4] = { Ah, Al, Bh, Bl };
    const int lds_[4]   = { lda, lda, ldb, ldb };
#pragma unroll
    for (int t = 0; t < 4; ++t) {
        const bf16* s = srcs[t];
        const int ld = lds_[t];
        const uint32_t tb = sbuf + (uint32_t)t * TILE_BYTES;
#pragma unroll
        for (int h = 0; h < 2; ++h) {
            const int idx = tid + h * 256;      // 0..511
            const int r = idx >> 2;             // row 0..127
            const int q = idx & 3;              // 16B quarter within 64B row
            cp16(tb + (uint32_t)(r * ROWB + q * 16), s + (size_t)r * ld + k0 + q * 8);
        }
    }
}

// ---------------- per-chunk compute: 2 k16-steps x 16 tiles x 3 split-MMAs ----------------
__device__ __forceinline__ void compute_chunk(float (&c)[4][4][4], uint32_t sbuf,
                                              int wm, int wn, int lane)
{
    const int g = lane >> 2, t = lane & 3;
#pragma unroll
    for (int ks = 0; ks < 2; ++ks) {
        const int kb = ks * 16;
        uint32_t ah[4][4], al[4][4], bh[4][2], bl[4][2];
#pragma unroll
        for (int mt = 0; mt < 4; ++mt) {
            const int row = wm * 64 + mt * 16 + g;
            const uint32_t base = sbuf + (uint32_t)(row * ROWB + (kb + 2 * t) * 2);
            ah[mt][0] = lds_u32(base);
            ah[mt][1] = lds_u32(base + 8 * ROWB);
            ah[mt][2] = lds_u32(base + 16);
            ah[mt][3] = lds_u32(base + 8 * ROWB + 16);
            const uint32_t basel = base + TILE_BYTES;
            al[mt][0] = lds_u32(basel);
            al[mt][1] = lds_u32(basel + 8 * ROWB);
            al[mt][2] = lds_u32(basel + 16);
            al[mt][3] = lds_u32(basel + 8 * ROWB + 16);
        }
#pragma unroll
        for (int nt = 0; nt < 4; ++nt) {
            const int row = wn * 32 + nt * 8 + g;
            const uint32_t base = sbuf + 2 * TILE_BYTES + (uint32_t)(row * ROWB + (kb + 2 * t) * 2);
            bh[nt][0] = lds_u32(base);
            bh[nt][1] = lds_u32(base + 16);
            bl[nt][0] = lds_u32(base + TILE_BYTES);
            bl[nt][1] = lds_u32(base + TILE_BYTES + 16);
        }
#pragma unroll
        for (int mt = 0; mt < 4; ++mt)
#pragma unroll
            for (int nt = 0; nt < 4; ++nt) {
                float* cc = c[mt][nt];
                mma16816(cc, ah[mt][0], ah[mt][1], ah[mt][2], ah[mt][3], bh[nt][0], bh[nt][1]);
                mma16816(cc, ah[mt][0], ah[mt][1], ah[mt][2], ah[mt][3], bl[nt][0], bl[nt][1]);
                mma16816(cc, al[mt][0], al[mt][1], al[mt][2], al[mt][3], bh[nt][0], bh[nt][1]);
            }
    }
}

// ---------------- generic double-buffered mainloop ----------------
__device__ __forceinline__ void gemm_loop(float (&c)[4][4][4],
    const bf16* __restrict__ Ah, const bf16* __restrict__ Al, int lda,
    const bf16* __restrict__ Bh, const bf16* __restrict__ Bl, int ldb,
    int K, uint32_t sb)
{
    const int tid = threadIdx.x;
    const int lane = tid & 31, wid = tid >> 5;
    const int wm = wid & 1, wn = wid >> 1;
    const int nch = K / CHUNK;

    load_chunk(sb, Ah, Al, lda, Bh, Bl, ldb, 0, tid);
    cp_commit();
#pragma unroll 1
    for (int ch = 0; ch < nch; ++ch) {
        if (ch + 1 < nch) {
            load_chunk(sb + (uint32_t)((ch + 1) & 1) * BUF_BYTES, Ah, Al, lda, Bh, Bl, ldb,
                       (ch + 1) * CHUNK, tid);
            cp_commit();
            cp_wait<1>();
        } else {
            cp_wait<0>();
        }
        __syncthreads();
        compute_chunk(c, sb + (uint32_t)(ch & 1) * BUF_BYTES, wm, wn, lane);
        __syncthreads();
    }
}

__device__ __forceinline__ void store_split(bf16* __restrict__ H, bf16* __restrict__ L,
                                            size_t off, float v0, float v1) {
    const bf16 h0 = __float2bfloat16(v0);
    const bf16 h1 = __float2bfloat16(v1);
    const bf16 l0 = __float2bfloat16(v0 - __bfloat162float(h0));
    const bf16 l1 = __float2bfloat16(v1 - __bfloat162float(h1));
    __nv_bfloat162 hp; hp.x = h0; hp.y = h1;
    __nv_bfloat162 lp; lp.x = l0; lp.y = l1;
    *reinterpret_cast<__nv_bfloat162*>(H + off) = hp;
    *reinterpret_cast<__nv_bfloat162*>(L + off) = lp;
}

// ---------------- kernel 1: QKV GEMM ----------------
__global__ __launch_bounds__(256, 1) void k_gemm_qkv(const float* __restrict__ bias) {
    extern __shared__ char smp[];
    const uint32_t sb = smem_u32(smp);
    const int m0 = blockIdx.y * 128, n0 = blockIdx.x * 128;
    const int lane = threadIdx.x & 31, wid = threadIdx.x >> 5;
    const int wm = wid & 1, wn = wid >> 1;
    const int g = lane >> 2, t = lane & 3;

    float c[4][4][4];
#pragma unroll
    for (int i = 0; i < 4; ++i)
#pragma unroll
        for (int j = 0; j < 4; ++j)
#pragma unroll
            for (int k = 0; k < 4; ++k) c[i][j][k] = 0.0f;

    gemm_loop(c, g_xh + (size_t)m0 * DD, g_xl + (size_t)m0 * DD, DD,
              g_wh + (size_t)n0 * DD, g_wl + (size_t)n0 * DD, DD, DD, sb);

#pragma unroll
    for (int mt = 0; mt < 4; ++mt)
#pragma unroll
        for (int nt = 0; nt < 4; ++nt)
#pragma unroll
            for (int h = 0; h < 2; ++h) {
                const int m = m0 + wm * 64 + mt * 16 + g + h * 8;
                const int n = n0 + wn * 32 + nt * 8 + 2 * t;
                const float v0 = c[mt][nt][h * 2 + 0] + bias[n];
                const float v1 = c[mt][nt][h * 2 + 1] + bias[n + 1];
                store_split(g_qkvh, g_qkvl, (size_t)m * QKV_LD + n, v0, v1);
            }
}

// ---------------- kernel 2: scores GEMM (causal) ----------------
__global__ __launch_bounds__(256, 1) void k_gemm_scores() {
    const int b = blockIdx.z, it = blockIdx.y, jt = blockIdx.x;
    if (jt > it) return;

    extern __shared__ char smp[];
    const uint32_t sb = smem_u32(smp);
    const int i0 = it * 128, j0 = jt * 128;
    const int lane = threadIdx.x & 31, wid = threadIdx.x >> 5;
    const int wm = wid & 1, wn = wid >> 1;
    const int g = lane >> 2, t = lane & 3;
    const size_t rowb = (size_t)b * TT;

    float c[4][4][4];
#pragma unroll
    for (int i = 0; i < 4; ++i)
#pragma unroll
        for (int j = 0; j < 4; ++j)
#pragma unroll
            for (int k = 0; k < 4; ++k) c[i][j][k] = 0.0f;

    gemm_loop(c, g_qkvh + (rowb + i0) * QKV_LD, g_qkvl + (rowb + i0) * QKV_LD, QKV_LD,
              g_qkvh + (rowb + j0) * QKV_LD + 1024, g_qkvl + (rowb + j0) * QKV_LD + 1024, QKV_LD,
              DD, sb);

    const bool diag = (it == jt);
#pragma unroll
    for (int mt = 0; mt < 4; ++mt)
#pragma unroll
        for (int nt = 0; nt < 4; ++nt)
#pragma unroll
            for (int h = 0; h < 2; ++h) {
                const int gi = i0 + wm * 64 + mt * 16 + g + h * 8;
                const int gj = j0 + wn * 32 + nt * 8 + 2 * t;
                float v0 = c[mt][nt][h * 2 + 0] * INV_SCALE;
                float v1 = c[mt][nt][h * 2 + 1] * INV_SCALE;
                if (diag) {
                    if (gj > gi) v0 = 0.0f;
                    if (gj + 1 > gi) v1 = 0.0f;
                }
                store_split(g_sh, g_sl, (size_t)b * TT * TT + (size_t)gi * TT + gj, v0, v1);
            }
}

// ---------------- kernel 3: y = S @ V (pre-transposed V) ----------------
__global__ __launch_bounds__(256, 1) void k_gemm_attnv() {
    const int b = blockIdx.z, it = blockIdx.y, dt = blockIdx.x;

    extern __shared__ char smp[];
    const uint32_t sb = smem_u32(smp);
    const int i0 = it * 128, d0 = dt * 128;
    const int lane = threadIdx.x & 31, wid = threadIdx.x >> 5;
    const int wm = wid & 1, wn = wid >> 1;
    const int g = lane >> 2, t = lane & 3;
    const int K = (it + 1) * 128;

    float c[4][4][4];
#pragma unroll
    for (int i = 0; i < 4; ++i)
#pragma unroll
        for (int j = 0; j < 4; ++j)
#pragma unroll
            for (int k = 0; k < 4; ++k) c[i][j][k] = 0.0f;

    gemm_loop(c, g_sh + (size_t)b * TT * TT + (size_t)i0 * TT,
                 g_sl + (size_t)b * TT * TT + (size_t)i0 * TT, TT,
                 g_vth + (size_t)b * DD * TT + (size_t)d0 * TT,
                 g_vtl + (size_t)b * DD * TT + (size_t)d0 * TT, TT, K, sb);

#pragma unroll
    for (int mt = 0; mt < 4; ++mt)
#pragma unroll
        for (int nt = 0; nt < 4; ++nt)
#pragma unroll
            for (int h = 0; h < 2; ++h) {
                const int m = b * TT + i0 + wm * 64 + mt * 16 + g + h * 8;
                const int n = d0 + wn * 32 + nt * 8 + 2 * t;
                float2 v; v.x = c[mt][nt][h * 2 + 0]; v.y = c[mt][nt][h * 2 + 1];
                *reinterpret_cast<float2*>(g_y + (size_t)m * DD + n) = v;
            }
}

// ---------------- split fp32 -> bf16 hi/lo ----------------
__global__ __launch_bounds__(256) void k_split(const float* __restrict__ in,
                                               bf16* __restrict__ hi, bf16* __restrict__ lo) {
    const int i = blockIdx.x * 256 + threadIdx.x;
    const float4 v = reinterpret_cast<const float4*>(in)[i];
    float a[4] = { v.x, v.y, v.z, v.w };
    ushort4 hv, lv;
    unsigned short* hp = &hv.x;
    unsigned short* lp = &lv.x;
#pragma unroll
    for (int j = 0; j < 4; ++j) {
        bf16 h = __float2bfloat16(a[j]);
        bf16 l = __float2bfloat16(a[j] - __bfloat162float(h));
        hp[j] = *reinterpret_cast<unsigned short*>(&h);
        lp[j] = *reinterpret_cast<unsigned short*>(&l);
    }
    reinterpret_cast<ushort4*>(hi)[i] = hv;
    reinterpret_cast<ushort4*>(lo)[i] = lv;
}

// ---------------- transpose V: qkv[...,2048+d] -> vt[b][d][j] ----------------
__global__ __launch_bounds__(256) void k_trans_v() {
    __shared__ bf16 t[32][33];
    const int b = blockIdx.z >> 1, arr = blockIdx.z & 1;
    const bf16* in = (arr ? g_qkvl : g_qkvh) + (size_t)b * TT * QKV_LD + 2048;
    bf16* out = (arr ? g_vtl : g_vth) + (size_t)b * DD * TT;
    const int j0 = blockIdx.x * 32, d0 = blockIdx.y * 32;
    const int tx = threadIdx.x & 31, ty = threadIdx.x >> 5;
#pragma unroll
    for (int y = ty; y < 32; y += 8) t[y][tx] = in[(size_t)(j0 + y) * QKV_LD + d0 + tx];
    __syncthreads();
#pragma unroll
    for (int y = ty; y < 32; y += 8) out[(size_t)(d0 + y) * TT + j0 + tx] = t[tx][y];
}

// ---------------- LayerNorm ----------------
__global__ __launch_bounds__(256) void k_ln(const float* __restrict__ lnw,
                                            const float* __restrict__ lnb,
                                            float* __restrict__ out) {
    const int row = blockIdx.x;
    const int tid = threadIdx.x;
    const float4 v = ((const float4*)(g_y + (size_t)row * DD))[tid];

    __shared__ float sh[8];
    __shared__ float sh2[8];
    const int wid = tid >> 5, lid = tid & 31;

    float s = v.x + v.y + v.z + v.w;
#pragma unroll
    for (int o = 16; o; o >>= 1) s += __shfl_xor_sync(0xffffffffu, s, o);
    if (lid == 0) sh[wid] = s;
    __syncthreads();
    float mean = 0.0f;
#pragma unroll
    for (int w = 0; w < 8; w++) mean += sh[w];
    mean *= (1.0f / 1024.0f);

    const float dx = v.x - mean, dy = v.y - mean, dz = v.z - mean, dw = v.w - mean;
    float ss = dx * dx + dy * dy + dz * dz + dw * dw;
#pragma unroll
    for (int o = 16; o; o >>= 1) ss += __shfl_xor_sync(0xffffffffu, ss, o);
    if (lid == 0) sh2[wid] = ss;
    __syncthreads();
    float var = 0.0f;
#pragma unroll
    for (int w = 0; w < 8; w++) var += sh2[w];
    var *= (1.0f / 1024.0f);

    const float rstd = rsqrtf(var + 1e-5f);
    const int c = tid * 4;
    float4 o4;
    o4.x = dx * rstd * lnw[c + 0] + lnb[c + 0];
    o4.y = dy * rstd * lnw[c + 1] + lnb[c + 1];
    o4.z = dz * rstd * lnw[c + 2] + lnb[c + 2];
    o4.w = dw * rstd * lnw[c + 3] + lnb[c + 3];
    ((float4*)(out + (size_t)row * DD))[tid] = o4;
}

// ---------------- launch ----------------
extern "C" void kernel_launch(void* const* d_in, const int* in_sizes, int n_in,
                              void* d_out, int out_size) {
    (void)in_sizes; (void)n_in; (void)out_size;
    const float* x    = (const float*)d_in[0];
    const float* W    = (const float*)d_in[1];
    const float* bias = (const float*)d_in[2];
    const float* lnw  = (const float*)d_in[3];
    const float* lnb  = (const float*)d_in[4];
    float* out = (float*)d_out;

    static int attr_done = 0;
    if (!attr_done) {  // first call is the non-captured correctness run
        cudaFuncSetAttribute(k_gemm_qkv,    cudaFuncAttributeMaxDynamicSharedMemorySize, SMEM_DYN);
        cudaFuncSetAttribute(k_gemm_scores, cudaFuncAttributeMaxDynamicSharedMemorySize, SMEM_DYN);
        cudaFuncSetAttribute(k_gemm_attnv,  cudaFuncAttributeMaxDynamicSharedMemorySize, SMEM_DYN);
        attr_done = 1;
    }

    bf16* xh; bf16* xl; bf16* wh; bf16* wl;
    cudaGetSymbolAddress((void**)&xh, g_xh);
    cudaGetSymbolAddress((void**)&xl, g_xl);
    cudaGetSymbolAddress((void**)&wh, g_wh);
    cudaGetSymbolAddress((void**)&wl, g_wl);

    k_split<<<(MTOT * DD / 4) / 256, 256>>>(x, xh, xl);
    k_split<<<(3 * DD * DD / 4) / 256, 256>>>(W, wh, wl);
    k_gemm_qkv<<<dim3(QKV_LD / 128, MTOT / 128), 256, SMEM_DYN>>>(bias);
    k_trans_v<<<dim3(TT / 32, DD / 32, BB * 2), 256>>>();
    k_gemm_scores<<<dim3(TT / 128, TT / 128, BB), 256, SMEM_DYN>>>();
    k_gemm_attnv<<<dim3(DD / 128, TT / 128, BB), 256, SMEM_DYN>>>();
    k_ln<<<MTOT, 256>>>(lnw, lnb, out);
}